// round 17
// baseline (speedup 1.0000x reference)
#include <cuda_runtime.h>
#include <math.h>
#include <stdint.h>

#define B_N 4096
#define D_N 16384

#define EPOCH_STEP (2.0 / 49.0)
#define W_FIRST_D  (2.0 - 10.0 * EPOCH_STEP)   /* ~1.5918367346938775 */
#define W_LAST_D   (2.0 - W_FIRST_D)
#define BATCH_STEP_D ((W_FIRST_D - W_LAST_D) / (double)(B_N - 1))

// Sortable u32 keys: raw IEEE bits of difficulty (always > 0 -> order-preserving).
__device__ __align__(16) unsigned int g_keys[B_N];

// Per-chunk completion counters + rank-block completion counter.
// Invariant: all zero at every kernel_launch entry; last rank block resets.
#define N_CHUNKS 4
#define CHUNK_ROWS (B_N / N_CHUNKS)            // 1024
__device__ unsigned int g_chunk_done[N_CHUNKS] = {0, 0, 0, 0};
__device__ unsigned int g_rank_done = 0;

#define THREADS 128
#define N_RANK 512                             // rank blocks (bid 0..511)
#define IPB (B_N / N_RANK)                     // 8 i's per rank block

// ---------------------------------------------------------------------------
// Fused kernel with chunked producer/consumer overlap.
//  bid <  N_RANK : rank block. Waits per-chunk; counts pairs against chunk c
//                  as soon as its keys are published (overlapped with the
//                  remaining norm streaming). Epilogue: weight + atomicAdd.
//  bid >= N_RANK : phase-1 block, row = bid - N_RANK. Computes difficulty,
//                  publishes key, bumps its chunk counter, exits.
// Rank blocks are scheduled FIRST (low bids -> resident from wave 1).
// Deadlock-free: 10 blocks/SM x 148 SMs = 1480 slots > 512 spinners.
// ---------------------------------------------------------------------------
__global__ __launch_bounds__(THREADS, 10) void fused_kernel(
    const float* __restrict__ loss,
    const float4* __restrict__ grad,       // [B, D/4]
    float* __restrict__ out)               // out[0]=weighted_loss, out[1..B]=difficulty
{
    const int bid = blockIdx.x;
    const int tid = threadIdx.x;

    if (bid >= N_RANK) {
        // ================= Phase-1 block: one row =================
        const int row = bid - N_RANK;
        const float4* __restrict__ g = grad + (size_t)row * (D_N / 4);

        float s0 = 0.0f, s1 = 0.0f, s2 = 0.0f, s3 = 0.0f;
#pragma unroll
        for (int it = 0; it < 8; it++) {       // 32 float4 per thread
            float4 a = __ldcs(&g[tid + (it * 4 + 0) * THREADS]);
            float4 b = __ldcs(&g[tid + (it * 4 + 1) * THREADS]);
            float4 c = __ldcs(&g[tid + (it * 4 + 2) * THREADS]);
            float4 d = __ldcs(&g[tid + (it * 4 + 3) * THREADS]);
            s0 = fmaf(a.x, a.x, s0); s0 = fmaf(a.y, a.y, s0);
            s0 = fmaf(a.z, a.z, s0); s0 = fmaf(a.w, a.w, s0);
            s1 = fmaf(b.x, b.x, s1); s1 = fmaf(b.y, b.y, s1);
            s1 = fmaf(b.z, b.z, s1); s1 = fmaf(b.w, b.w, s1);
            s2 = fmaf(c.x, c.x, s2); s2 = fmaf(c.y, c.y, s2);
            s2 = fmaf(c.z, c.z, s2); s2 = fmaf(c.w, c.w, s2);
            s3 = fmaf(d.x, d.x, s3); s3 = fmaf(d.y, d.y, s3);
            s3 = fmaf(d.z, d.z, s3); s3 = fmaf(d.w, d.w, s3);
        }
        float s = (s0 + s1) + (s2 + s3);

#pragma unroll
        for (int off = 16; off > 0; off >>= 1)
            s += __shfl_xor_sync(0xFFFFFFFFu, s, off);

        __shared__ float warp_sums[THREADS / 32];
        if ((tid & 31) == 0) warp_sums[tid >> 5] = s;
        __syncthreads();

        if (tid == 0) {
            float tot = warp_sums[0] + warp_sums[1] + warp_sums[2] + warp_sums[3];
            float d = 0.5f * __ldg(&loss[row]) + 0.5f * sqrtf(tot);
            out[1 + row] = d;
            g_keys[row] = __float_as_uint(d);
            __threadfence();                               // publish key
            atomicAdd(&g_chunk_done[row >> 10], 1u);       // bump chunk counter
        }
        return;
    }

    // ================= Rank block =================
    const int i0 = bid * IPB;
    const int ci = i0 >> 10;                   // chunk containing our i's

    if (bid == 0 && tid == 0) out[0] = 0.0f;   // reset accumulator (runs in wave 1,
                                               // long before any rank epilogue atomic)

    // Prefetch loss values (independent of keys).
    float lv[IPB];
    if (tid == 0) {
#pragma unroll
        for (int k = 0; k < IPB; k++) lv[k] = __ldg(&loss[i0 + k]);
    }

    __shared__ unsigned int s_go;

    // Wait for our own chunk, then load our keys.
    if (tid == 0) {
        while (*(volatile unsigned int*)&g_chunk_done[ci] < (unsigned)CHUNK_ROWS)
            __nanosleep(64);
        s_go = 1u;
    }
    __syncthreads();
    __threadfence();   // acquire published keys of chunk ci

    unsigned int ki[IPB];
#pragma unroll
    for (int k = 0; k < IPB; k++) ki[k] = g_keys[i0 + k];

    int cnt[IPB];
#pragma unroll
    for (int k = 0; k < IPB; k++) cnt[k] = 0;

    // Process chunks in order; each becomes available while phase 1 streams on.
    for (int c = 0; c < N_CHUNKS; c++) {
        if (tid == 0) {
            while (*(volatile unsigned int*)&g_chunk_done[c] < (unsigned)CHUNK_ROWS)
                __nanosleep(64);
            s_go = 1u;
        }
        __syncthreads();
        __threadfence();   // acquire chunk c's keys

        const uint4* __restrict__ keys4 =
            (const uint4*)g_keys + c * (CHUNK_ROWS / 4);
#pragma unroll
        for (int p = tid; p < CHUNK_ROWS / 4; p += THREADS) {   // 2 iters
            uint4 v = keys4[p];
#pragma unroll
            for (int k = 0; k < IPB; k++) {
                cnt[k] += (v.x < ki[k]);
                cnt[k] += (v.y < ki[k]);
                cnt[k] += (v.z < ki[k]);
                cnt[k] += (v.w < ki[k]);
            }
        }
    }

    // REDUX warp reduction
#pragma unroll
    for (int k = 0; k < IPB; k++)
        cnt[k] = __reduce_add_sync(0xFFFFFFFFu, cnt[k]);

    __shared__ int warp_cnt[THREADS / 32][IPB];
    if ((tid & 31) == 0) {
#pragma unroll
        for (int k = 0; k < IPB; k++)
            warp_cnt[tid >> 5][k] = cnt[k];
    }
    __syncthreads();

    if (tid == 0) {
        float contrib = 0.0f;
#pragma unroll
        for (int k = 0; k < IPB; k++) {
            int rank = warp_cnt[0][k] + warp_cnt[1][k] + warp_cnt[2][k] + warp_cnt[3][k];
            float w = (float)(W_FIRST_D - BATCH_STEP_D * (double)rank);
            contrib += lv[k] * w;
        }
        atomicAdd(&out[0], contrib * (1.0f / (float)B_N));

        // Last rank block resets all counters for the next graph replay.
        // By then every rank block has passed all chunk waits.
        unsigned int r = atomicAdd(&g_rank_done, 1u);
        if (r == (unsigned)(N_RANK - 1)) {
#pragma unroll
            for (int c = 0; c < N_CHUNKS; c++) g_chunk_done[c] = 0u;
            g_rank_done = 0u;
        }
    }
}

// ---------------------------------------------------------------------------
extern "C" void kernel_launch(void* const* d_in, const int* in_sizes, int n_in,
                              void* d_out, int out_size)
{
    const float*  loss = (const float*)d_in[0];
    const float4* grad = (const float4*)d_in[1];
    float* out = (float*)d_out;

    fused_kernel<<<N_RANK + B_N, THREADS>>>(loss, grad, out);
}